// round 16
// baseline (speedup 1.0000x reference)
#include <cuda_runtime.h>
#include <cuda_bf16.h>

#define NN 100000
#define NE_MAX 1600000
#define INC 64
#define HIDC 128
#define OUTC 64
#define NCLS 20
#define NCHUNK 98          // ceil(NN/1024)

// ---------------- device scratch (static globals; no allocation) ------------
__device__ int   g_is64;
__device__ int   g_cnt;
__device__ int   g_degi[NN];
__device__ int   g_rowstart[NN];
__device__ int   g_cursor[NN];
__device__ int   g_srclist[NE_MAX];
__device__ float g_dinv[NN];
__device__ __align__(16) float g_sp[(size_t)NN * HIDC];    // [s2 | p] fp32
__device__ __align__(16) float g_wcat1[HIDC * HIDC];       // tf32 [Ws1;Wn1]
__device__ __align__(16) float g_wcat2[HIDC * HIDC];       // tf32 [Ws2|Wn2]

// ---------------- helpers ----------------------------------------------------

__device__ __forceinline__ unsigned f2tf32(float f) {
    unsigned r; asm("cvt.rna.tf32.f32 %0, %1;" : "=r"(r) : "f"(f)); return r;
}
__device__ __forceinline__ float ftf(float f) { return __uint_as_float(f2tf32(f)); }

__device__ __forceinline__ void mma_tf32(float4& d,
                                         unsigned a0, unsigned a1, unsigned a2, unsigned a3,
                                         unsigned b0, unsigned b1) {
    asm("mma.sync.aligned.m16n8k8.row.col.f32.tf32.tf32.f32 "
        "{%0,%1,%2,%3}, {%4,%5,%6,%7}, {%8,%9}, {%0,%1,%2,%3};"
        : "+f"(d.x), "+f"(d.y), "+f"(d.z), "+f"(d.w)
        : "r"(a0), "r"(a1), "r"(a2), "r"(a3), "r"(b0), "r"(b1));
}

__device__ __forceinline__ void cp16(void* smem, const void* g) {
    unsigned s = (unsigned)__cvta_generic_to_shared(smem);
    asm volatile("cp.async.cg.shared.global [%0], [%1], 16;" :: "r"(s), "l"(g));
}
__device__ __forceinline__ void cp_commit() { asm volatile("cp.async.commit_group;"); }
__device__ __forceinline__ void cp_wait1()  { asm volatile("cp.async.wait_group 1;" ::: "memory"); }
__device__ __forceinline__ void cp_wait0()  { asm volatile("cp.async.wait_group 0;" ::: "memory"); }

// ---------------- init / prep kernels ----------------------------------------

__global__ void k_init(const int* __restrict__ ei32, int n32,
                       int* __restrict__ flag, int* __restrict__ degi,
                       int* __restrict__ cnt) {
    int i = blockIdx.x * blockDim.x + threadIdx.x;
    if (i < NN) degi[i] = 0;
    if (i == 0) *cnt = 0;
    if (blockIdx.x == 0) {
        __shared__ int s_any;
        if (threadIdx.x == 0) s_any = 0;
        __syncthreads();
        int nonzero = 0;
        int limit = n32 < 16384 ? n32 : 16384;
        for (int k = 1 + 2 * threadIdx.x; k < limit; k += 2 * blockDim.x)
            if (ei32[k] != 0) nonzero = 1;
        if (nonzero) atomicOr(&s_any, 1);
        __syncthreads();
        if (threadIdx.x == 0) *flag = (s_any == 0) ? 1 : 0;
    }
}

__global__ void k_prepW(const float* __restrict__ ws1, const float* __restrict__ wn1,
                        const float* __restrict__ ws2, const float* __restrict__ wn2,
                        float* __restrict__ wcat1, float* __restrict__ wcat2) {
    int idx = blockIdx.x * blockDim.x + threadIdx.x;
    if (idx >= 2 * HIDC * HIDC) return;
    int m = idx >> 14;
    int rem = idx & 16383;
    int k = rem >> 7, j = rem & 127;
    float v;
    if (m == 0) v = (k < 64) ? ws1[k * HIDC + j] : wn1[(k - 64) * HIDC + j];
    else        v = (j < 64) ? ws2[k * OUTC + j] : wn2[k * OUTC + (j - 64)];
    (m == 0 ? wcat1 : wcat2)[rem] = ftf(v);
}

// ---------------- CSR build kernels ------------------------------------------

__global__ void k_convert(const void* __restrict__ ei, int nE,
                          int* __restrict__ degi, const int* __restrict__ flag) {
    int e = blockIdx.x * blockDim.x + threadIdx.x;
    if (e >= nE) return;
    int d = (*flag) ? (int)((const long long*)ei)[(long long)nE + e]
                    : ((const int*)ei)[nE + e];
    if ((unsigned)d >= NN) d = 0;
    atomicAdd(&degi[d], 1);
}

__global__ __launch_bounds__(1024) void k_offsets(const int* __restrict__ degi,
                                                  int* __restrict__ rowstart,
                                                  int* __restrict__ cursor,
                                                  float* __restrict__ dinv,
                                                  int* __restrict__ cnt) {
    __shared__ int s[1024];
    __shared__ int sbase;
    int tid = threadIdx.x;
    int i = blockIdx.x * 1024 + tid;
    int v = (i < NN) ? degi[i] : 0;
    s[tid] = v;
    __syncthreads();
    for (int off = 1; off < 1024; off <<= 1) {
        int t = (tid >= off) ? s[tid - off] : 0;
        __syncthreads();
        s[tid] += t;
        __syncthreads();
    }
    if (tid == 1023) sbase = atomicAdd(cnt, s[1023]);
    __syncthreads();
    if (i < NN) {
        int excl = sbase + s[tid] - v;
        rowstart[i] = excl;
        cursor[i] = excl;
        dinv[i] = 1.0f / fmaxf((float)v, 1.0f);
    }
}

__global__ void k_scatter(const void* __restrict__ ei, int nE,
                          int* __restrict__ cursor, int* __restrict__ srclist,
                          const int* __restrict__ flag) {
    int e = blockIdx.x * blockDim.x + threadIdx.x;
    if (e >= nE) return;
    int s, d;
    if (*flag) {
        s = (int)((const long long*)ei)[e];
        d = (int)((const long long*)ei)[(long long)nE + e];
    } else {
        s = ((const int*)ei)[e];
        d = ((const int*)ei)[nE + e];
    }
    if ((unsigned)s >= NN) s = 0;
    if ((unsigned)d >= NN) d = 0;
    int p = atomicAdd(&cursor[d], 1);
    srclist[p] = s;
}

// ---------------- gather2: p-agg + layer2 epilogue + classifier ---------------

__global__ __launch_bounds__(256) void k_gather2(
    const float4* __restrict__ sp, const int* __restrict__ rowstart,
    const int* __restrict__ degi, const int* __restrict__ srclist,
    const float* __restrict__ dinv, const float4* __restrict__ b2,
    const float* __restrict__ wc, const float* __restrict__ bc,
    float* __restrict__ out) {
    __shared__ float sWcT[NCLS * 64];   // transposed: [cls][k], 5 KB
    __shared__ float sBc[NCLS];
    const int tid = threadIdx.x;
    for (int i = tid; i < NCLS * 64; i += 256) {
        int cls = i >> 6, k = i & 63;
        sWcT[i] = wc[k * NCLS + cls];
    }
    if (tid < NCLS) sBc[tid] = bc[tid];
    __syncthreads();

    int node = blockIdx.x * 8 + (tid >> 5);
    if (node >= NN) return;
    int lane = tid & 31;
    int half = lane >> 4;
    int c = lane & 15;
    int beg = rowstart[node];
    int cnt = degi[node];
    float4 acc = make_float4(0.f, 0.f, 0.f, 0.f);
    float4 acc2 = make_float4(0.f, 0.f, 0.f, 0.f);
    int i = half;
    for (; i + 2 < cnt; i += 4) {
        int s0 = __ldg(&srclist[beg + i]);
        int s1 = __ldg(&srclist[beg + i + 2]);
        float4 v0 = __ldg(&sp[(long long)s0 * 32 + 16 + c]);
        float4 v1 = __ldg(&sp[(long long)s1 * 32 + 16 + c]);
        acc.x += v0.x; acc.y += v0.y; acc.z += v0.z; acc.w += v0.w;
        acc2.x += v1.x; acc2.y += v1.y; acc2.z += v1.z; acc2.w += v1.w;
    }
    for (; i < cnt; i += 2) {
        int s = __ldg(&srclist[beg + i]);
        float4 v = __ldg(&sp[(long long)s * 32 + 16 + c]);
        acc.x += v.x; acc.y += v.y; acc.z += v.z; acc.w += v.w;
    }
    acc.x += acc2.x; acc.y += acc2.y; acc.z += acc2.z; acc.w += acc2.w;
    acc.x += __shfl_xor_sync(0xffffffffu, acc.x, 16);
    acc.y += __shfl_xor_sync(0xffffffffu, acc.y, 16);
    acc.z += __shfl_xor_sync(0xffffffffu, acc.z, 16);
    acc.w += __shfl_xor_sync(0xffffffffu, acc.w, 16);

    float di = dinv[node];
    float4 sv = __ldg(&sp[(long long)node * 32 + c]);
    float4 bv = __ldg(&b2[c]);
    float4 r;
    r.x = fmaxf(sv.x + acc.x * di + bv.x, 0.f);
    r.y = fmaxf(sv.y + acc.y * di + bv.y, 0.f);
    r.z = fmaxf(sv.z + acc.z * di + bv.z, 0.f);
    r.w = fmaxf(sv.w + acc.w * di + bv.w, 0.f);

    const int clsbase = half * 10;
    float part[10];
#pragma unroll
    for (int t = 0; t < 10; t++) {
        float4 w = *(const float4*)&sWcT[(clsbase + t) * 64 + 4 * c];
        part[t] = r.x * w.x + r.y * w.y + r.z * w.z + r.w * w.w;
    }
#pragma unroll
    for (int m = 1; m <= 8; m <<= 1)
#pragma unroll
        for (int t = 0; t < 10; t++)
            part[t] += __shfl_xor_sync(0xffffffffu, part[t], m);
    if (c == 0) {
#pragma unroll
        for (int t = 0; t < 10; t++)
            out[(long long)node * NCLS + clsbase + t] = part[t] + sBc[clsbase + t];
    }
}

// ---------------- MEGA-FUSED: gather1 + layer1 GEMM + layer2 GEMM -------------
// A region: 4 slices of 128x32 (stride 36): [x kp0 | x kp1 | agg kp2 | agg kp3]
//   x slices: raw fp32 via cp.async, tf32-cvt applied at fragment read.
//   agg slices: gathered in-kernel, tf32-rounded at write.
// Stage 1 -> h1 tile in smem (aliases A region). Stage 2 -> sp global.
#define SA_S 36
#define SW_S 136
#define TILE_A_WORDS (128 * SA_S)     // 4608
#define TILE_W_WORDS (32 * SW_S)      // 4352
#define AREG_WORDS (4 * TILE_A_WORDS) // 18432
#define H1T_S 132
#define H1T_WORDS (128 * H1T_S)       // 16896 (<= AREG_WORDS, aliases)
#define FUSED_SMEM_WORDS (AREG_WORDS + 2 * TILE_W_WORDS)  // 27136
#define FUSED_SMEM_BYTES (FUSED_SMEM_WORDS * 4)           // 108544 (~106 KB)

__device__ __forceinline__ void load_w(unsigned* bufW, int kp, const float* Wc, int tid) {
#pragma unroll
    for (int t = 0; t < 4; t++) {
        int idx = tid + t * 256;
        int kk = idx >> 5, c4 = idx & 31;
        cp16(&bufW[kk * SW_S + c4 * 4], &Wc[(long long)(kp * 32 + kk) * 128 + c4 * 4]);
    }
}

__global__ __launch_bounds__(256) void k_fused(
    const float* __restrict__ x,
    const int* __restrict__ rowstart, const int* __restrict__ degi,
    const int* __restrict__ srclist, const float* __restrict__ dinv,
    const float* __restrict__ Wcat1, const float* __restrict__ Wcat2,
    const float* __restrict__ bias, float* __restrict__ sp) {
    extern __shared__ unsigned smem[];
    unsigned* areg = smem;                                  // 4 A slices
    unsigned* wring[2] = { smem + AREG_WORDS, smem + AREG_WORDS + TILE_W_WORDS };
    unsigned* h1t = smem;                                   // aliases A region
    const int tid = threadIdx.x;
    const int lane = tid & 31;
    const int wrp = tid >> 5;
    const int gid = lane >> 2;
    const int tig = lane & 3;
    const int wm = wrp * 16;
    const int n0 = blockIdx.x * 128;

    // issue x slices (kp 0,1 raw fp32) + W1 slice 0
#pragma unroll
    for (int kp = 0; kp < 2; kp++) {
#pragma unroll
        for (int t = 0; t < 4; t++) {
            int idx = tid + t * 256;
            int row = idx >> 3, c4 = idx & 7;
            int grow = n0 + row; if (grow >= NN) grow = NN - 1;
            cp16(&areg[kp * TILE_A_WORDS + row * SA_S + c4 * 4],
                 &x[(long long)grow * INC + kp * 32 + c4 * 4]);
        }
    }
    load_w(wring[0], 0, Wcat1, tid);
    cp_commit();

    // ---- in-block gather: agg rows n0..n0+127 -> A slices 2,3 (tf32) ----
    {
        const int half = lane >> 4;
        const int c = lane & 15;
        unsigned* Gs = areg + (2 + (c >> 3)) * TILE_A_WORDS;
        const int c4 = c & 7;
        const float4* featx = (const float4*)x;
        for (int t = 0; t < 16; t++) {
            int node = n0 + wm + t;
            if (node >= NN) break;
            int beg = rowstart[node];
            int cnt = degi[node];
            float4 acc = make_float4(0.f, 0.f, 0.f, 0.f);
            float4 acc2 = make_float4(0.f, 0.f, 0.f, 0.f);
            int i = half;
            for (; i + 2 < cnt; i += 4) {
                int s0 = __ldg(&srclist[beg + i]);
                int s1 = __ldg(&srclist[beg + i + 2]);
                float4 v0 = __ldg(&featx[(long long)s0 * 16 + c]);
                float4 v1 = __ldg(&featx[(long long)s1 * 16 + c]);
                acc.x += v0.x; acc.y += v0.y; acc.z += v0.z; acc.w += v0.w;
                acc2.x += v1.x; acc2.y += v1.y; acc2.z += v1.z; acc2.w += v1.w;
            }
            for (; i < cnt; i += 2) {
                int s = __ldg(&srclist[beg + i]);
                float4 v = __ldg(&featx[(long long)s * 16 + c]);
                acc.x += v.x; acc.y += v.y; acc.z += v.z; acc.w += v.w;
            }
            acc.x += acc2.x; acc.y += acc2.y; acc.z += acc2.z; acc.w += acc2.w;
            acc.x += __shfl_xor_sync(0xffffffffu, acc.x, 16);
            acc.y += __shfl_xor_sync(0xffffffffu, acc.y, 16);
            acc.z += __shfl_xor_sync(0xffffffffu, acc.z, 16);
            acc.w += __shfl_xor_sync(0xffffffffu, acc.w, 16);
            if (half == 0) {
                float di = dinv[node];
                uint4 u;
                u.x = f2tf32(acc.x * di); u.y = f2tf32(acc.y * di);
                u.z = f2tf32(acc.z * di); u.w = f2tf32(acc.w * di);
                *(uint4*)&Gs[(wm + t) * SA_S + c4 * 4] = u;
            }
        }
    }
    __syncthreads();

    float4 acc[16];
#pragma unroll
    for (int t = 0; t < 16; t++) acc[t] = make_float4(0.f, 0.f, 0.f, 0.f);

    // ---- stage 1 (W1 double-buffered; A all-resident) ----
#pragma unroll
    for (int kp = 0; kp < 4; kp++) {
        if (kp < 3) {
            load_w(wring[(kp + 1) & 1], kp + 1, Wcat1, tid);
            cp_commit();
            cp_wait1();
        } else {
            cp_wait0();
        }
        __syncthreads();
        unsigned* sA = areg + kp * TILE_A_WORDS;
        unsigned* sW = wring[kp & 1];
#pragma unroll
        for (int ks = 0; ks < 4; ks++) {
            unsigned a0 = sA[(wm + gid) * SA_S + ks * 8 + tig];
            unsigned a1 = sA[(wm + gid + 8) * SA_S + ks * 8 + tig];
            unsigned a2 = sA[(wm + gid) * SA_S + ks * 8 + tig + 4];
            unsigned a3 = sA[(wm + gid + 8) * SA_S + ks * 8 + tig + 4];
            if (kp < 2) {   // x slices are raw fp32 -> tf32 at read
                a0 = f2tf32(__uint_as_float(a0));
                a1 = f2tf32(__uint_as_float(a1));
                a2 = f2tf32(__uint_as_float(a2));
                a3 = f2tf32(__uint_as_float(a3));
            }
#pragma unroll
            for (int nt = 0; nt < 16; nt++) {
                unsigned b0 = sW[(ks * 8 + tig) * SW_S + nt * 8 + gid];
                unsigned b1 = sW[(ks * 8 + tig + 4) * SW_S + nt * 8 + gid];
                mma_tf32(acc[nt], a0, a1, a2, a3, b0, b1);
            }
        }
        __syncthreads();
    }

    // ---- transition: first w2 slice, h1 tile to smem (aliases A region) ----
    load_w(wring[0], 0, Wcat2, tid);
    cp_commit();
#pragma unroll
    for (int nt = 0; nt < 16; nt++) {
        int col = nt * 8 + 2 * tig;
        float2 bb = __ldg((const float2*)&bias[col]);
        unsigned* r0p = &h1t[(wm + gid) * H1T_S + col];
        unsigned* r1p = &h1t[(wm + gid + 8) * H1T_S + col];
        r0p[0] = f2tf32(fmaxf(acc[nt].x + bb.x, 0.f));
        r0p[1] = f2tf32(fmaxf(acc[nt].y + bb.y, 0.f));
        r1p[0] = f2tf32(fmaxf(acc[nt].z + bb.x, 0.f));
        r1p[1] = f2tf32(fmaxf(acc[nt].w + bb.y, 0.f));
    }
#pragma unroll
    for (int t = 0; t < 16; t++) acc[t] = make_float4(0.f, 0.f, 0.f, 0.f);
    __syncthreads();

    // ---- stage 2 ----
#pragma unroll
    for (int kp = 0; kp < 4; kp++) {
        if (kp < 3) {
            load_w(wring[(kp + 1) & 1], kp + 1, Wcat2, tid);
            cp_commit();
            cp_wait1();
        } else {
            cp_wait0();
        }
        __syncthreads();
        unsigned* sW = wring[kp & 1];
#pragma unroll
        for (int ks = 0; ks < 4; ks++) {
            unsigned a0 = h1t[(wm + gid) * H1T_S + kp * 32 + ks * 8 + tig];
            unsigned a1 = h1t[(wm + gid + 8) * H1T_S + kp * 32 + ks * 8 + tig];
            unsigned a2 = h1t[(wm + gid) * H1T_S + kp * 32 + ks * 8 + tig + 4];
            unsigned a3 = h1t[(wm + gid + 8) * H1T_S + kp * 32 + ks * 8 + tig + 4];
#pragma unroll
            for (int nt = 0; nt < 16; nt++) {
                unsigned b0 = sW[(ks * 8 + tig) * SW_S + nt * 8 + gid];
                unsigned b1 = sW[(ks * 8 + tig + 4) * SW_S + nt * 8 + gid];
                mma_tf32(acc[nt], a0, a1, a2, a3, b0, b1);
            }
        }
        __syncthreads();
    }

    int row0 = n0 + wm + gid;
    int row1 = row0 + 8;
#pragma unroll
    for (int nt = 0; nt < 16; nt++) {
        int col = nt * 8 + 2 * tig;
        if (row0 < NN)
            *(float2*)&sp[(long long)row0 * 128 + col] = make_float2(acc[nt].x, acc[nt].y);
        if (row1 < NN)
            *(float2*)&sp[(long long)row1 * 128 + col] = make_float2(acc[nt].z, acc[nt].w);
    }
}

// ---------------- launch ----------------------------------------------------
extern "C" void kernel_launch(void* const* d_in, const int* in_sizes, int n_in,
                              void* d_out, int out_size) {
    const float* x   = (const float*)d_in[0];
    const void*  ei  = d_in[1];
    const float* ws1 = (const float*)d_in[2];
    const float* wn1 = (const float*)d_in[3];
    const float* b1  = (const float*)d_in[4];
    const float* ws2 = (const float*)d_in[5];
    const float* wn2 = (const float*)d_in[6];
    const float* b2  = (const float*)d_in[7];
    const float* wc  = (const float*)d_in[8];
    const float* bc  = (const float*)d_in[9];
    float* out = (float*)d_out;

    int nE = in_sizes[1] / 2;
    if (nE > NE_MAX) nE = NE_MAX;

    void *p_flag, *p_cnt, *p_degi, *p_rs, *p_cur, *p_src;
    void *p_dinv, *p_sp, *p_w1, *p_w2;
    cudaGetSymbolAddress(&p_flag, g_is64);
    cudaGetSymbolAddress(&p_cnt,  g_cnt);
    cudaGetSymbolAddress(&p_degi, g_degi);
    cudaGetSymbolAddress(&p_rs,   g_rowstart);
    cudaGetSymbolAddress(&p_cur,  g_cursor);
    cudaGetSymbolAddress(&p_src,  g_srclist);
    cudaGetSymbolAddress(&p_dinv, g_dinv);
    cudaGetSymbolAddress(&p_sp,   g_sp);
    cudaGetSymbolAddress(&p_w1,   g_wcat1);
    cudaGetSymbolAddress(&p_w2,   g_wcat2);
    int*   flag  = (int*)p_flag;
    int*   cnt   = (int*)p_cnt;
    int*   degi  = (int*)p_degi;
    int*   rs    = (int*)p_rs;
    int*   cur   = (int*)p_cur;
    int*   src   = (int*)p_src;
    float* dinv  = (float*)p_dinv;
    float* sp    = (float*)p_sp;
    float* wcat1 = (float*)p_w1;
    float* wcat2 = (float*)p_w2;

    cudaFuncSetAttribute(k_fused, cudaFuncAttributeMaxDynamicSharedMemorySize,
                         FUSED_SMEM_BYTES);

    // init + weight prep
    k_init<<<(NN + 255) / 256, 256>>>((const int*)ei, in_sizes[1], flag, degi, cnt);
    k_prepW<<<(2 * HIDC * HIDC + 255) / 256, 256>>>(ws1, wn1, ws2, wn2, wcat1, wcat2);

    // CSR build
    k_convert<<<(nE + 255) / 256, 256>>>(ei, nE, degi, flag);
    k_offsets<<<NCHUNK, 1024>>>(degi, rs, cur, dinv, cnt);
    k_scatter<<<(nE + 255) / 256, 256>>>(ei, nE, cur, src, flag);

    // mega-fused: gather1 + layer1 + layer2 GEMMs
    k_fused<<<(NN + 127) / 128, 256, FUSED_SMEM_BYTES>>>(x, rs, degi, src, dinv,
                                                         wcat1, wcat2, b1, sp);

    // gather2 + epilogue + classifier
    k_gather2<<<(NN + 7) / 8, 256>>>((const float4*)sp, rs, degi, src, dinv,
                                     (const float4*)b2, wc, bc, out);
}

// round 17
// speedup vs baseline: 1.8112x; 1.8112x over previous
#include <cuda_runtime.h>
#include <cuda_bf16.h>

#define NN 100000
#define NE_MAX 1600000
#define INC 64
#define HIDC 128
#define OUTC 64
#define NCLS 20
#define NCHUNK 98          // ceil(NN/1024)

// ---------------- device scratch (static globals; no allocation) ------------
__device__ int   g_is64;
__device__ int   g_cnt;
__device__ int   g_degi[NN];
__device__ int   g_rowstart[NN];
__device__ int   g_cursor[NN];
__device__ int   g_srclist[NE_MAX];
__device__ float g_dinv[NN];
__device__ __align__(16) float g_agg1[(size_t)NN * INC];   // tf32-rounded agg*dinv
__device__ __align__(16) float g_sp[(size_t)NN * HIDC];    // [s2 | p] fp32
__device__ __align__(16) float g_wcat1[HIDC * HIDC];       // tf32 [Ws1;Wn1]
__device__ __align__(16) float g_wcat2[HIDC * HIDC];       // tf32 [Ws2|Wn2]

// ---------------- helpers ----------------------------------------------------

__device__ __forceinline__ unsigned f2tf32(float f) {
    unsigned r; asm("cvt.rna.tf32.f32 %0, %1;" : "=r"(r) : "f"(f)); return r;
}
__device__ __forceinline__ float ftf(float f) { return __uint_as_float(f2tf32(f)); }

__device__ __forceinline__ void mma_tf32(float4& d,
                                         unsigned a0, unsigned a1, unsigned a2, unsigned a3,
                                         unsigned b0, unsigned b1) {
    asm("mma.sync.aligned.m16n8k8.row.col.f32.tf32.tf32.f32 "
        "{%0,%1,%2,%3}, {%4,%5,%6,%7}, {%8,%9}, {%0,%1,%2,%3};"
        : "+f"(d.x), "+f"(d.y), "+f"(d.z), "+f"(d.w)
        : "r"(a0), "r"(a1), "r"(a2), "r"(a3), "r"(b0), "r"(b1));
}

__device__ __forceinline__ void cp16(void* smem, const void* g) {
    unsigned s = (unsigned)__cvta_generic_to_shared(smem);
    asm volatile("cp.async.cg.shared.global [%0], [%1], 16;" :: "r"(s), "l"(g));
}
__device__ __forceinline__ void cp_commit() { asm volatile("cp.async.commit_group;"); }
__device__ __forceinline__ void cp_wait1()  { asm volatile("cp.async.wait_group 1;" ::: "memory"); }
__device__ __forceinline__ void cp_wait0()  { asm volatile("cp.async.wait_group 0;" ::: "memory"); }

// ---------------- init / prep kernels ----------------------------------------

__global__ void k_init(const int* __restrict__ ei32, int n32,
                       int* __restrict__ flag, int* __restrict__ degi,
                       int* __restrict__ cnt) {
    int i = blockIdx.x * blockDim.x + threadIdx.x;
    if (i < NN) degi[i] = 0;
    if (i == 0) *cnt = 0;
    if (blockIdx.x == 0) {
        __shared__ int s_any;
        if (threadIdx.x == 0) s_any = 0;
        __syncthreads();
        int nonzero = 0;
        int limit = n32 < 16384 ? n32 : 16384;
        for (int k = 1 + 2 * threadIdx.x; k < limit; k += 2 * blockDim.x)
            if (ei32[k] != 0) nonzero = 1;
        if (nonzero) atomicOr(&s_any, 1);
        __syncthreads();
        if (threadIdx.x == 0) *flag = (s_any == 0) ? 1 : 0;
    }
}

__global__ void k_prepW(const float* __restrict__ ws1, const float* __restrict__ wn1,
                        const float* __restrict__ ws2, const float* __restrict__ wn2,
                        float* __restrict__ wcat1, float* __restrict__ wcat2) {
    int idx = blockIdx.x * blockDim.x + threadIdx.x;
    if (idx >= 2 * HIDC * HIDC) return;
    int m = idx >> 14;
    int rem = idx & 16383;
    int k = rem >> 7, j = rem & 127;
    float v;
    if (m == 0) v = (k < 64) ? ws1[k * HIDC + j] : wn1[(k - 64) * HIDC + j];
    else        v = (j < 64) ? ws2[k * OUTC + j] : wn2[k * OUTC + (j - 64)];
    (m == 0 ? wcat1 : wcat2)[rem] = ftf(v);
}

// ---------------- CSR build kernels ------------------------------------------

__global__ void k_convert(const void* __restrict__ ei, int nE,
                          int* __restrict__ degi, const int* __restrict__ flag) {
    int e = blockIdx.x * blockDim.x + threadIdx.x;
    if (e >= nE) return;
    int d = (*flag) ? (int)((const long long*)ei)[(long long)nE + e]
                    : ((const int*)ei)[nE + e];
    if ((unsigned)d >= NN) d = 0;
    atomicAdd(&degi[d], 1);
}

__global__ __launch_bounds__(1024) void k_offsets(const int* __restrict__ degi,
                                                  int* __restrict__ rowstart,
                                                  int* __restrict__ cursor,
                                                  float* __restrict__ dinv,
                                                  int* __restrict__ cnt) {
    __shared__ int s[1024];
    __shared__ int sbase;
    int tid = threadIdx.x;
    int i = blockIdx.x * 1024 + tid;
    int v = (i < NN) ? degi[i] : 0;
    s[tid] = v;
    __syncthreads();
    for (int off = 1; off < 1024; off <<= 1) {
        int t = (tid >= off) ? s[tid - off] : 0;
        __syncthreads();
        s[tid] += t;
        __syncthreads();
    }
    if (tid == 1023) sbase = atomicAdd(cnt, s[1023]);
    __syncthreads();
    if (i < NN) {
        int excl = sbase + s[tid] - v;
        rowstart[i] = excl;
        cursor[i] = excl;
        dinv[i] = 1.0f / fmaxf((float)v, 1.0f);
    }
}

__global__ void k_scatter(const void* __restrict__ ei, int nE,
                          int* __restrict__ cursor, int* __restrict__ srclist,
                          const int* __restrict__ flag) {
    int e = blockIdx.x * blockDim.x + threadIdx.x;
    if (e >= nE) return;
    int s, d;
    if (*flag) {
        s = (int)((const long long*)ei)[e];
        d = (int)((const long long*)ei)[(long long)nE + e];
    } else {
        s = ((const int*)ei)[e];
        d = ((const int*)ei)[nE + e];
    }
    if ((unsigned)s >= NN) s = 0;
    if ((unsigned)d >= NN) d = 0;
    int p = atomicAdd(&cursor[d], 1);
    srclist[p] = s;
}

// ---------------- gather kernels ---------------------------------------------

__global__ __launch_bounds__(256) void k_gather1(
    const float4* __restrict__ feat, const int* __restrict__ rowstart,
    const int* __restrict__ degi, const int* __restrict__ srclist,
    const float* __restrict__ dinv, float4* __restrict__ out) {
    int node = blockIdx.x * 8 + (threadIdx.x >> 5);
    if (node >= NN) return;
    int lane = threadIdx.x & 31;
    int half = lane >> 4;
    int c = lane & 15;
    int beg = rowstart[node];
    int cnt = degi[node];
    float4 acc = make_float4(0.f, 0.f, 0.f, 0.f);
    float4 acc2 = make_float4(0.f, 0.f, 0.f, 0.f);
    int i = half;
    for (; i + 2 < cnt; i += 4) {
        int s0 = __ldg(&srclist[beg + i]);
        int s1 = __ldg(&srclist[beg + i + 2]);
        float4 v0 = __ldg(&feat[(long long)s0 * 16 + c]);
        float4 v1 = __ldg(&feat[(long long)s1 * 16 + c]);
        acc.x += v0.x; acc.y += v0.y; acc.z += v0.z; acc.w += v0.w;
        acc2.x += v1.x; acc2.y += v1.y; acc2.z += v1.z; acc2.w += v1.w;
    }
    for (; i < cnt; i += 2) {
        int s = __ldg(&srclist[beg + i]);
        float4 v = __ldg(&feat[(long long)s * 16 + c]);
        acc.x += v.x; acc.y += v.y; acc.z += v.z; acc.w += v.w;
    }
    acc.x += acc2.x; acc.y += acc2.y; acc.z += acc2.z; acc.w += acc2.w;
    acc.x += __shfl_xor_sync(0xffffffffu, acc.x, 16);
    acc.y += __shfl_xor_sync(0xffffffffu, acc.y, 16);
    acc.z += __shfl_xor_sync(0xffffffffu, acc.z, 16);
    acc.w += __shfl_xor_sync(0xffffffffu, acc.w, 16);
    if (half == 0) {
        float di = dinv[node];
        out[(long long)node * 16 + c] =
            make_float4(ftf(acc.x * di), ftf(acc.y * di), ftf(acc.z * di), ftf(acc.w * di));
    }
}

// gather over p + layer2 epilogue + fused classifier
__global__ __launch_bounds__(256) void k_gather2(
    const float4* __restrict__ sp, const int* __restrict__ rowstart,
    const int* __restrict__ degi, const int* __restrict__ srclist,
    const float* __restrict__ dinv, const float4* __restrict__ b2,
    const float* __restrict__ wc, const float* __restrict__ bc,
    float* __restrict__ out) {
    __shared__ float sWcT[NCLS * 64];   // transposed: [cls][k], 5 KB
    __shared__ float sBc[NCLS];
    const int tid = threadIdx.x;
    for (int i = tid; i < NCLS * 64; i += 256) {
        int cls = i >> 6, k = i & 63;
        sWcT[i] = wc[k * NCLS + cls];
    }
    if (tid < NCLS) sBc[tid] = bc[tid];
    __syncthreads();

    int node = blockIdx.x * 8 + (tid >> 5);
    if (node >= NN) return;
    int lane = tid & 31;
    int half = lane >> 4;
    int c = lane & 15;
    int beg = rowstart[node];
    int cnt = degi[node];
    float4 acc = make_float4(0.f, 0.f, 0.f, 0.f);
    float4 acc2 = make_float4(0.f, 0.f, 0.f, 0.f);
    int i = half;
    for (; i + 2 < cnt; i += 4) {
        int s0 = __ldg(&srclist[beg + i]);
        int s1 = __ldg(&srclist[beg + i + 2]);
        float4 v0 = __ldg(&sp[(long long)s0 * 32 + 16 + c]);
        float4 v1 = __ldg(&sp[(long long)s1 * 32 + 16 + c]);
        acc.x += v0.x; acc.y += v0.y; acc.z += v0.z; acc.w += v0.w;
        acc2.x += v1.x; acc2.y += v1.y; acc2.z += v1.z; acc2.w += v1.w;
    }
    for (; i < cnt; i += 2) {
        int s = __ldg(&srclist[beg + i]);
        float4 v = __ldg(&sp[(long long)s * 32 + 16 + c]);
        acc.x += v.x; acc.y += v.y; acc.z += v.z; acc.w += v.w;
    }
    acc.x += acc2.x; acc.y += acc2.y; acc.z += acc2.z; acc.w += acc2.w;
    acc.x += __shfl_xor_sync(0xffffffffu, acc.x, 16);
    acc.y += __shfl_xor_sync(0xffffffffu, acc.y, 16);
    acc.z += __shfl_xor_sync(0xffffffffu, acc.z, 16);
    acc.w += __shfl_xor_sync(0xffffffffu, acc.w, 16);

    float di = dinv[node];
    float4 sv = __ldg(&sp[(long long)node * 32 + c]);
    float4 bv = __ldg(&b2[c]);
    float4 r;
    r.x = fmaxf(sv.x + acc.x * di + bv.x, 0.f);
    r.y = fmaxf(sv.y + acc.y * di + bv.y, 0.f);
    r.z = fmaxf(sv.z + acc.z * di + bv.z, 0.f);
    r.w = fmaxf(sv.w + acc.w * di + bv.w, 0.f);

    const int clsbase = half * 10;
    float part[10];
#pragma unroll
    for (int t = 0; t < 10; t++) {
        float4 w = *(const float4*)&sWcT[(clsbase + t) * 64 + 4 * c];
        part[t] = r.x * w.x + r.y * w.y + r.z * w.z + r.w * w.w;
    }
#pragma unroll
    for (int m = 1; m <= 8; m <<= 1)
#pragma unroll
        for (int t = 0; t < 10; t++)
            part[t] += __shfl_xor_sync(0xffffffffu, part[t], m);
    if (c == 0) {
#pragma unroll
        for (int t = 0; t < 10; t++)
            out[(long long)node * NCLS + clsbase + t] = part[t] + sBc[clsbase + t];
    }
}

// ---------------- FUSED double-GEMM ------------------------------------------
// Stage 1: h1_tile = relu(x@Wcat1[0:64] + agg1@Wcat1[64:128] + b1)  (tf32, smem)
//   x slices arrive raw fp32 (cvt at fragment read); agg1 pre-rounded tf32.
// Stage 2: sp_tile = h1_tile @ Wcat2    -> global (h1 never touches gmem)
#define SA_S 36
#define SW_S 136
#define TILE_A_WORDS (128 * SA_S)
#define TILE_W_WORDS (32 * SW_S)
#define BUF_WORDS (TILE_A_WORDS + TILE_W_WORDS)
#define H1T_S 132
#define H1T_WORDS (128 * H1T_S)
#define FUSED_SMEM_WORDS (H1T_WORDS + 2 * TILE_W_WORDS)  // 25600 (>= 2*BUF_WORDS)
#define FUSED_SMEM_BYTES (FUSED_SMEM_WORDS * 4)          // 100 KB

__device__ __forceinline__ void load_tiles1(
    unsigned* bufA, unsigned* bufW, int kp, int n0,
    const float* x, const float* agg1, const float* Wcat1, int tid) {
    const float* Asrc = (kp < 2) ? x : agg1;
    int colbase = (kp & 1) * 32;
#pragma unroll
    for (int t = 0; t < 4; t++) {
        int idx = tid + t * 256;
        int row = idx >> 3, c4 = idx & 7;
        int grow = n0 + row; if (grow >= NN) grow = NN - 1;
        cp16(&bufA[row * SA_S + c4 * 4], &Asrc[(long long)grow * INC + colbase + c4 * 4]);
    }
#pragma unroll
    for (int t = 0; t < 4; t++) {
        int idx = tid + t * 256;
        int kk = idx >> 5, c4 = idx & 31;
        cp16(&bufW[kk * SW_S + c4 * 4], &Wcat1[(long long)(kp * 32 + kk) * 128 + c4 * 4]);
    }
}

__device__ __forceinline__ void load_w2(unsigned* bufW, int kp, const float* Wcat2, int tid) {
#pragma unroll
    for (int t = 0; t < 4; t++) {
        int idx = tid + t * 256;
        int kk = idx >> 5, c4 = idx & 31;
        cp16(&bufW[kk * SW_S + c4 * 4], &Wcat2[(long long)(kp * 32 + kk) * 128 + c4 * 4]);
    }
}

__global__ __launch_bounds__(256) void k_gemm_fused(
    const float* __restrict__ x, const float* __restrict__ agg1,
    const float* __restrict__ Wcat1, const float* __restrict__ Wcat2,
    const float* __restrict__ bias, float* __restrict__ sp) {
    extern __shared__ unsigned smem[];
    unsigned* bA[2] = { smem, smem + BUF_WORDS };
    unsigned* bW[2] = { smem + TILE_A_WORDS, smem + BUF_WORDS + TILE_A_WORDS };
    unsigned* h1t = smem;                                  // aliases stage-1 bufs
    unsigned* w2b[2] = { smem + H1T_WORDS, smem + H1T_WORDS + TILE_W_WORDS };
    const int tid = threadIdx.x;
    const int lane = tid & 31;
    const int wrp = tid >> 5;
    const int gid = lane >> 2;
    const int tig = lane & 3;
    const int wm = wrp * 16;
    const int n0 = blockIdx.x * 128;

    float4 acc[16];
#pragma unroll
    for (int t = 0; t < 16; t++) acc[t] = make_float4(0.f, 0.f, 0.f, 0.f);

    // ---- stage 1 ----
    load_tiles1(bA[0], bW[0], 0, n0, x, agg1, Wcat1, tid);
    cp_commit();
#pragma unroll
    for (int kp = 0; kp < 4; kp++) {
        if (kp < 3) {
            load_tiles1(bA[(kp + 1) & 1], bW[(kp + 1) & 1], kp + 1, n0, x, agg1, Wcat1, tid);
            cp_commit();
            cp_wait1();
        } else {
            cp_wait0();
        }
        __syncthreads();
        unsigned* sA = bA[kp & 1];
        unsigned* sW = bW[kp & 1];
#pragma unroll
        for (int ks = 0; ks < 4; ks++) {
            unsigned a0 = sA[(wm + gid) * SA_S + ks * 8 + tig];
            unsigned a1 = sA[(wm + gid + 8) * SA_S + ks * 8 + tig];
            unsigned a2 = sA[(wm + gid) * SA_S + ks * 8 + tig + 4];
            unsigned a3 = sA[(wm + gid + 8) * SA_S + ks * 8 + tig + 4];
            if (kp < 2) {   // x slices are raw fp32 -> tf32 at read
                a0 = f2tf32(__uint_as_float(a0));
                a1 = f2tf32(__uint_as_float(a1));
                a2 = f2tf32(__uint_as_float(a2));
                a3 = f2tf32(__uint_as_float(a3));
            }
#pragma unroll
            for (int nt = 0; nt < 16; nt++) {
                unsigned b0 = sW[(ks * 8 + tig) * SW_S + nt * 8 + gid];
                unsigned b1 = sW[(ks * 8 + tig + 4) * SW_S + nt * 8 + gid];
                mma_tf32(acc[nt], a0, a1, a2, a3, b0, b1);
            }
        }
        __syncthreads();
    }

    // ---- transition: issue first w2 slice, write h1 tile to smem ----
    load_w2(w2b[0], 0, Wcat2, tid);
    cp_commit();
#pragma unroll
    for (int nt = 0; nt < 16; nt++) {
        int col = nt * 8 + 2 * tig;
        float2 bb = __ldg((const float2*)&bias[col]);
        unsigned* r0p = &h1t[(wm + gid) * H1T_S + col];
        unsigned* r1p = &h1t[(wm + gid + 8) * H1T_S + col];
        r0p[0] = f2tf32(fmaxf(acc[nt].x + bb.x, 0.f));
        r0p[1] = f2tf32(fmaxf(acc[nt].y + bb.y, 0.f));
        r1p[0] = f2tf32(fmaxf(acc[nt].z + bb.x, 0.f));
        r1p[1] = f2tf32(fmaxf(acc[nt].w + bb.y, 0.f));
    }
#pragma unroll
    for (int t = 0; t < 16; t++) acc[t] = make_float4(0.f, 0.f, 0.f, 0.f);
    __syncthreads();

    // ---- stage 2 ----
#pragma unroll
    for (int kp = 0; kp < 4; kp++) {
        if (kp < 3) {
            load_w2(w2b[(kp + 1) & 1], kp + 1, Wcat2, tid);
            cp_commit();
            cp_wait1();
        } else {
            cp_wait0();
        }
        __syncthreads();
        unsigned* sW = w2b[kp & 1];
#pragma unroll
        for (int ks = 0; ks < 4; ks++) {
            unsigned a0 = h1t[(wm + gid) * H1T_S + kp * 32 + ks * 8 + tig];
            unsigned a1 = h1t[(wm + gid + 8) * H1T_S + kp * 32 + ks * 8 + tig];
            unsigned a2 = h1t[(wm + gid) * H1T_S + kp * 32 + ks * 8 + tig + 4];
            unsigned a3 = h1t[(wm + gid + 8) * H1T_S + kp * 32 + ks * 8 + tig + 4];
#pragma unroll
            for (int nt = 0; nt < 16; nt++) {
                unsigned b0 = sW[(ks * 8 + tig) * SW_S + nt * 8 + gid];
                unsigned b1 = sW[(ks * 8 + tig + 4) * SW_S + nt * 8 + gid];
                mma_tf32(acc[nt], a0, a1, a2, a3, b0, b1);
            }
        }
        __syncthreads();
    }

    int row0 = n0 + wm + gid;
    int row1 = row0 + 8;
#pragma unroll
    for (int nt = 0; nt < 16; nt++) {
        int col = nt * 8 + 2 * tig;
        if (row0 < NN)
            *(float2*)&sp[(long long)row0 * 128 + col] = make_float2(acc[nt].x, acc[nt].y);
        if (row1 < NN)
            *(float2*)&sp[(long long)row1 * 128 + col] = make_float2(acc[nt].z, acc[nt].w);
    }
}

// ---------------- launch ----------------------------------------------------
extern "C" void kernel_launch(void* const* d_in, const int* in_sizes, int n_in,
                              void* d_out, int out_size) {
    const float* x   = (const float*)d_in[0];
    const void*  ei  = d_in[1];
    const float* ws1 = (const float*)d_in[2];
    const float* wn1 = (const float*)d_in[3];
    const float* b1  = (const float*)d_in[4];
    const float* ws2 = (const float*)d_in[5];
    const float* wn2 = (const float*)d_in[6];
    const float* b2  = (const float*)d_in[7];
    const float* wc  = (const float*)d_in[8];
    const float* bc  = (const float*)d_in[9];
    float* out = (float*)d_out;

    int nE = in_sizes[1] / 2;
    if (nE > NE_MAX) nE = NE_MAX;

    void *p_flag, *p_cnt, *p_degi, *p_rs, *p_cur, *p_src;
    void *p_dinv, *p_agg1, *p_sp, *p_w1, *p_w2;
    cudaGetSymbolAddress(&p_flag, g_is64);
    cudaGetSymbolAddress(&p_cnt,  g_cnt);
    cudaGetSymbolAddress(&p_degi, g_degi);
    cudaGetSymbolAddress(&p_rs,   g_rowstart);
    cudaGetSymbolAddress(&p_cur,  g_cursor);
    cudaGetSymbolAddress(&p_src,  g_srclist);
    cudaGetSymbolAddress(&p_dinv, g_dinv);
    cudaGetSymbolAddress(&p_agg1, g_agg1);
    cudaGetSymbolAddress(&p_sp,   g_sp);
    cudaGetSymbolAddress(&p_w1,   g_wcat1);
    cudaGetSymbolAddress(&p_w2,   g_wcat2);
    int*   flag  = (int*)p_flag;
    int*   cnt   = (int*)p_cnt;
    int*   degi  = (int*)p_degi;
    int*   rs    = (int*)p_rs;
    int*   cur   = (int*)p_cur;
    int*   src   = (int*)p_src;
    float* dinv  = (float*)p_dinv;
    float* agg1  = (float*)p_agg1;
    float* sp    = (float*)p_sp;
    float* wcat1 = (float*)p_w1;
    float* wcat2 = (float*)p_w2;

    cudaFuncSetAttribute(k_gemm_fused, cudaFuncAttributeMaxDynamicSharedMemorySize,
                         FUSED_SMEM_BYTES);

    // init + weight prep
    k_init<<<(NN + 255) / 256, 256>>>((const int*)ei, in_sizes[1], flag, degi, cnt);
    k_prepW<<<(2 * HIDC * HIDC + 255) / 256, 256>>>(ws1, wn1, ws2, wn2, wcat1, wcat2);

    // CSR build
    k_convert<<<(nE + 255) / 256, 256>>>(ei, nE, degi, flag);
    k_offsets<<<NCHUNK, 1024>>>(degi, rs, cur, dinv, cnt);
    k_scatter<<<(nE + 255) / 256, 256>>>(ei, nE, cur, src, flag);

    // layer 1 gather
    k_gather1<<<(NN + 7) / 8, 256>>>((const float4*)x, rs, degi, src, dinv,
                                     (float4*)agg1);

    // fused layer1+layer2 GEMM (x raw fp32, cvt at read)
    k_gemm_fused<<<(NN + 127) / 128, 256, FUSED_SMEM_BYTES>>>(x, agg1, wcat1, wcat2,
                                                              b1, sp);

    // gather2 + epilogue + classifier
    k_gather2<<<(NN + 7) / 8, 256>>>((const float4*)sp, rs, degi, src, dinv,
                                     (const float4*)b2, wc, bc, out);
}